// round 1
// baseline (speedup 1.0000x reference)
#include <cuda_runtime.h>

#define NN 262144
#define EE 4194304
#define GG 1024

// Scratch (static __device__ — no allocation allowed)
__device__ float  g_deg[NN];
__device__ float  g_dinv[NN];
__device__ float4 g_h[NN * 4];     // node features as 4x float4 (16 floats)
__device__ float4 g_agg[NN * 4];
__device__ float4 g_pooled[GG * 4];

__device__ __forceinline__ float lrelu(float x) {
    return x >= 0.0f ? x : 0.01f * x;
}

// ---------------------------------------------------------------------------
// K0: deg = 1.0 (self loop)
__global__ void k_init_deg() {
    int i = blockIdx.x * blockDim.x + threadIdx.x;
    if (i < NN) g_deg[i] = 1.0f;
}

// K1: deg[dst] += ew
__global__ void k_deg(const int* __restrict__ dst, const float* __restrict__ ew) {
    int e = blockIdx.x * blockDim.x + threadIdx.x;
    if (e < EE) atomicAdd(&g_deg[dst[e]], ew[e]);
}

// K2: dinv = rsqrt(deg); h1 = X @ W1; agg = h1 * dinv^2  (self-loop term)
__global__ void k_layer1_pre(const float* __restrict__ X, const float* __restrict__ W1) {
    __shared__ float sW[48];
    if (threadIdx.x < 48) sW[threadIdx.x] = W1[threadIdx.x];
    __syncthreads();
    int i = blockIdx.x * blockDim.x + threadIdx.x;
    if (i >= NN) return;
    float di = rsqrtf(g_deg[i]);
    g_dinv[i] = di;
    float di2 = di * di;
    float x0 = X[i * 3 + 0], x1 = X[i * 3 + 1], x2 = X[i * 3 + 2];
#pragma unroll
    for (int c = 0; c < 4; c++) {
        float4 h;
        h.x = x0 * sW[4 * c + 0] + x1 * sW[16 + 4 * c + 0] + x2 * sW[32 + 4 * c + 0];
        h.y = x0 * sW[4 * c + 1] + x1 * sW[16 + 4 * c + 1] + x2 * sW[32 + 4 * c + 1];
        h.z = x0 * sW[4 * c + 2] + x1 * sW[16 + 4 * c + 2] + x2 * sW[32 + 4 * c + 2];
        h.w = x0 * sW[4 * c + 3] + x1 * sW[16 + 4 * c + 3] + x2 * sW[32 + 4 * c + 3];
        g_h[i * 4 + c] = h;
        float4 a = make_float4(h.x * di2, h.y * di2, h.z * di2, h.w * di2);
        g_agg[i * 4 + c] = a;
    }
}

// K3/K5: edge scatter. 4 threads per edge, each handles one float4 chunk.
// agg[dst] += h[src] * (dinv[src]*ew*dinv[dst])   via red.global.add.v4.f32
__global__ void k_edge(const int* __restrict__ src, const int* __restrict__ dst,
                       const float* __restrict__ ew) {
    unsigned int t = blockIdx.x * blockDim.x + threadIdx.x;
    if (t >= 4u * EE) return;
    int e = (int)(t >> 2);
    int c = (int)(t & 3u);
    int s = __ldg(&src[e]);
    int d = __ldg(&dst[e]);
    float nrm = __ldg(&g_dinv[s]) * __ldg(&ew[e]) * __ldg(&g_dinv[d]);
    float4 h = g_h[s * 4 + c];
    float4* p = &g_agg[d * 4 + c];
    asm volatile("red.global.add.v4.f32 [%0], {%1, %2, %3, %4};" ::
                 "l"(p), "f"(h.x * nrm), "f"(h.y * nrm), "f"(h.z * nrm), "f"(h.w * nrm)
                 : "memory");
}

// K4: v = leaky(agg1 + b1); h2 = v @ W2; agg2 = h2 * dinv^2
__global__ void k_layer2_pre(const float* __restrict__ W2, const float* __restrict__ b1) {
    __shared__ float sW[256];
    __shared__ float sb[16];
    for (int t = threadIdx.x; t < 256; t += blockDim.x) sW[t] = W2[t];
    if (threadIdx.x < 16) sb[threadIdx.x] = b1[threadIdx.x];
    __syncthreads();
    int i = blockIdx.x * blockDim.x + threadIdx.x;
    if (i >= NN) return;
    float v[16];
#pragma unroll
    for (int c = 0; c < 4; c++) {
        float4 a = g_agg[i * 4 + c];
        v[4 * c + 0] = lrelu(a.x + sb[4 * c + 0]);
        v[4 * c + 1] = lrelu(a.y + sb[4 * c + 1]);
        v[4 * c + 2] = lrelu(a.z + sb[4 * c + 2]);
        v[4 * c + 3] = lrelu(a.w + sb[4 * c + 3]);
    }
    float di = g_dinv[i];
    float di2 = di * di;
#pragma unroll
    for (int c = 0; c < 4; c++) {
        float h0 = 0.f, h1 = 0.f, h2 = 0.f, h3 = 0.f;
#pragma unroll
        for (int k = 0; k < 16; k++) {
            float vk = v[k];
            h0 += vk * sW[k * 16 + 4 * c + 0];
            h1 += vk * sW[k * 16 + 4 * c + 1];
            h2 += vk * sW[k * 16 + 4 * c + 2];
            h3 += vk * sW[k * 16 + 4 * c + 3];
        }
        g_h[i * 4 + c] = make_float4(h0, h1, h2, h3);
        g_agg[i * 4 + c] = make_float4(h0 * di2, h1 * di2, h2 * di2, h3 * di2);
    }
}

// K6: out2 = leaky(agg2 + b2)  -> stored into g_h (h2 no longer needed)
__global__ void k_post2(const float* __restrict__ b2) {
    __shared__ float sb[16];
    if (threadIdx.x < 16) sb[threadIdx.x] = b2[threadIdx.x];
    __syncthreads();
    int i = blockIdx.x * blockDim.x + threadIdx.x;
    if (i >= NN) return;
#pragma unroll
    for (int c = 0; c < 4; c++) {
        float4 a = g_agg[i * 4 + c];
        g_h[i * 4 + c] = make_float4(lrelu(a.x + sb[4 * c + 0]),
                                     lrelu(a.y + sb[4 * c + 1]),
                                     lrelu(a.z + sb[4 * c + 2]),
                                     lrelu(a.w + sb[4 * c + 3]));
    }
}

// K7: mean pool per graph. One block (128 threads) per graph; segment found by
// binary search over sorted Batching. No atomics.
__global__ void k_pool(const int* __restrict__ B) {
    int g = blockIdx.x;
    // lower_bound(g) and lower_bound(g+1)
    int lo = 0, hi = NN;
    while (lo < hi) { int m = (lo + hi) >> 1; if (__ldg(&B[m]) < g) lo = m + 1; else hi = m; }
    int start = lo;
    lo = start; hi = NN;
    while (lo < hi) { int m = (lo + hi) >> 1; if (__ldg(&B[m]) < g + 1) lo = m + 1; else hi = m; }
    int end = lo;
    int cnt = end - start;

    int c = threadIdx.x & 3;
    int k = threadIdx.x >> 2;  // 0..31
    float4 acc = make_float4(0.f, 0.f, 0.f, 0.f);
    for (int n = start + k; n < end; n += 32) {
        float4 v = g_h[n * 4 + c];
        acc.x += v.x; acc.y += v.y; acc.z += v.z; acc.w += v.w;
    }
    __shared__ float4 sm[128];
    sm[threadIdx.x] = acc;
    __syncthreads();
#pragma unroll
    for (int off = 64; off >= 4; off >>= 1) {
        if (threadIdx.x < off) {
            float4 o = sm[threadIdx.x + off];
            float4 m = sm[threadIdx.x];
            sm[threadIdx.x] = make_float4(m.x + o.x, m.y + o.y, m.z + o.z, m.w + o.w);
        }
        __syncthreads();
    }
    if (threadIdx.x < 4) {
        float inv = 1.0f / fmaxf((float)cnt, 1.0f);
        float4 s = sm[threadIdx.x];
        g_pooled[g * 4 + threadIdx.x] = make_float4(s.x * inv, s.y * inv, s.z * inv, s.w * inv);
    }
}

// K8: MLP heads. One thread per graph.
__global__ void k_mlp(const float* __restrict__ Wp1, const float* __restrict__ bp1,
                      const float* __restrict__ Wp2, const float* __restrict__ bp2,
                      const float* __restrict__ Wp3, const float* __restrict__ bp3,
                      const float* __restrict__ Wt1, const float* __restrict__ bt1,
                      const float* __restrict__ Wt2, const float* __restrict__ bt2,
                      const float* __restrict__ Wt3, const float* __restrict__ bt3,
                      float* __restrict__ out) {
    // shared weight cache
    __shared__ float sWp1[256], sWp2[256], sWp3[32], sWt1[256], sWt2[256], sWt3[32];
    __shared__ float sbp1[16], sbp2[16], sbp3[2], sbt1[16], sbt2[16], sbt3[2];
    for (int t = threadIdx.x; t < 256; t += blockDim.x) {
        sWp1[t] = Wp1[t]; sWp2[t] = Wp2[t]; sWt1[t] = Wt1[t]; sWt2[t] = Wt2[t];
    }
    if (threadIdx.x < 32) { sWp3[threadIdx.x] = Wp3[threadIdx.x]; sWt3[threadIdx.x] = Wt3[threadIdx.x]; }
    if (threadIdx.x < 16) {
        sbp1[threadIdx.x] = bp1[threadIdx.x]; sbp2[threadIdx.x] = bp2[threadIdx.x];
        sbt1[threadIdx.x] = bt1[threadIdx.x]; sbt2[threadIdx.x] = bt2[threadIdx.x];
    }
    if (threadIdx.x < 2) { sbp3[threadIdx.x] = bp3[threadIdx.x]; sbt3[threadIdx.x] = bt3[threadIdx.x]; }
    __syncthreads();

    int g = blockIdx.x * blockDim.x + threadIdx.x;
    if (g >= GG) return;
    float p[16];
#pragma unroll
    for (int c = 0; c < 4; c++) {
        float4 v = g_pooled[g * 4 + c];
        p[4 * c + 0] = v.x; p[4 * c + 1] = v.y; p[4 * c + 2] = v.z; p[4 * c + 3] = v.w;
    }
    float a[16], b[16];
    // Phi head
#pragma unroll
    for (int j = 0; j < 16; j++) {
        float s = sbp1[j];
#pragma unroll
        for (int k = 0; k < 16; k++) s += p[k] * sWp1[k * 16 + j];
        a[j] = lrelu(s);
    }
#pragma unroll
    for (int j = 0; j < 16; j++) {
        float s = sbp2[j];
#pragma unroll
        for (int k = 0; k < 16; k++) s += a[k] * sWp2[k * 16 + j];
        b[j] = lrelu(s);
    }
    float phi0 = sbp3[0], phi1 = sbp3[1];
#pragma unroll
    for (int k = 0; k < 16; k++) { phi0 += b[k] * sWp3[k * 2 + 0]; phi1 += b[k] * sWp3[k * 2 + 1]; }
    // Theta head
#pragma unroll
    for (int j = 0; j < 16; j++) {
        float s = sbt1[j];
#pragma unroll
        for (int k = 0; k < 16; k++) s += p[k] * sWt1[k * 16 + j];
        a[j] = lrelu(s);
    }
#pragma unroll
    for (int j = 0; j < 16; j++) {
        float s = sbt2[j];
#pragma unroll
        for (int k = 0; k < 16; k++) s += a[k] * sWt2[k * 16 + j];
        b[j] = lrelu(s);
    }
    float th0 = sbt3[0], th1 = sbt3[1];
#pragma unroll
    for (int k = 0; k < 16; k++) { th0 += b[k] * sWt3[k * 2 + 0]; th1 += b[k] * sWt3[k * 2 + 1]; }

    out[g * 4 + 0] = phi0;
    out[g * 4 + 1] = phi1;
    out[g * 4 + 2] = th0;
    out[g * 4 + 3] = th1;
}

// ---------------------------------------------------------------------------
extern "C" void kernel_launch(void* const* d_in, const int* in_sizes, int n_in,
                              void* d_out, int out_size) {
    const float* X   = (const float*)d_in[0];
    const int*   ei  = (const int*)d_in[1];     // [2, E] int32
    const float* ew  = (const float*)d_in[2];
    const int*   Bt  = (const int*)d_in[3];
    int base = 4;
    // skip scalar num_graphs input if present
    if (base < n_in && in_sizes[base] == 1) base++;
    const float* W1  = (const float*)d_in[base + 0];
    const float* b1  = (const float*)d_in[base + 1];
    const float* W2  = (const float*)d_in[base + 2];
    const float* b2  = (const float*)d_in[base + 3];
    const float* Wp1 = (const float*)d_in[base + 4];
    const float* bp1 = (const float*)d_in[base + 5];
    const float* Wp2 = (const float*)d_in[base + 6];
    const float* bp2 = (const float*)d_in[base + 7];
    const float* Wp3 = (const float*)d_in[base + 8];
    const float* bp3 = (const float*)d_in[base + 9];
    const float* Wt1 = (const float*)d_in[base + 10];
    const float* bt1 = (const float*)d_in[base + 11];
    const float* Wt2 = (const float*)d_in[base + 12];
    const float* bt2 = (const float*)d_in[base + 13];
    const float* Wt3 = (const float*)d_in[base + 14];
    const float* bt3 = (const float*)d_in[base + 15];

    const int* src = ei;
    const int* dst = ei + EE;
    float* out = (float*)d_out;

    k_init_deg<<<NN / 256, 256>>>();
    k_deg<<<EE / 256, 256>>>(dst, ew);
    k_layer1_pre<<<NN / 256, 256>>>(X, W1);
    k_edge<<<(4u * EE) / 256, 256>>>(src, dst, ew);
    k_layer2_pre<<<NN / 256, 256>>>(W2, b1);
    k_edge<<<(4u * EE) / 256, 256>>>(src, dst, ew);
    k_post2<<<NN / 256, 256>>>(b2);
    k_pool<<<GG, 128>>>(Bt);
    k_mlp<<<(GG + 255) / 256, 256>>>(Wp1, bp1, Wp2, bp2, Wp3, bp3,
                                     Wt1, bt1, Wt2, bt2, Wt3, bt3, out);
}

// round 2
// speedup vs baseline: 1.3299x; 1.3299x over previous
#include <cuda_runtime.h>

#define NN 262144
#define EE 4194304
#define GG 1024

// Scratch (static __device__ — no allocation allowed)
__device__ float  g_deg[NN];
__device__ float  g_dinv[NN];
__device__ float4 g_Xp[NN];        // X padded to float4 (w=0)
__device__ float4 g_aggX[NN];      // layer-1 raw aggregate of X
__device__ float  g_we[EE];        // per-edge ew * dinv[src]
__device__ float4 g_h[NN * 4];     // node features, 16 floats as 4x float4
__device__ float4 g_agg[NN * 4];   // layer-2 raw aggregate
__device__ float4 g_pooled[GG * 4];

__device__ __forceinline__ float lrelu(float x) {
    return x >= 0.0f ? x : 0.01f * x;
}

// ---------------------------------------------------------------------------
// K0: deg = 1.0 (self loop), aggX = 0
__global__ void k_init() {
    int i = blockIdx.x * blockDim.x + threadIdx.x;
    if (i < NN) {
        g_deg[i] = 1.0f;
        g_aggX[i] = make_float4(0.f, 0.f, 0.f, 0.f);
    }
}

// K1: deg[dst] += ew  (4 edges per thread, vectorized loads)
__global__ void k_deg(const int* __restrict__ dst, const float* __restrict__ ew) {
    int t = blockIdx.x * blockDim.x + threadIdx.x;
    if (t * 4 >= EE) return;
    int4   d4 = ((const int4*)dst)[t];
    float4 w4 = ((const float4*)ew)[t];
    atomicAdd(&g_deg[d4.x], w4.x);
    atomicAdd(&g_deg[d4.y], w4.y);
    atomicAdd(&g_deg[d4.z], w4.z);
    atomicAdd(&g_deg[d4.w], w4.w);
}

// K2: dinv = rsqrt(deg); Xp = pad(X)
__global__ void k_prep(const float* __restrict__ X) {
    int i = blockIdx.x * blockDim.x + threadIdx.x;
    if (i >= NN) return;
    g_dinv[i] = rsqrtf(g_deg[i]);
    g_Xp[i] = make_float4(X[i * 3 + 0], X[i * 3 + 1], X[i * 3 + 2], 0.0f);
}

// K3: layer-1 edge scatter on raw X (3-dim). One thread per edge.
// w = ew * dinv[src]; store g_we; aggX[dst] += w * Xp[src]   (dinv[dst] applied later)
__global__ void __launch_bounds__(256) k_edge1(const int* __restrict__ src,
                                               const int* __restrict__ dst,
                                               const float* __restrict__ ew) {
    int e = blockIdx.x * blockDim.x + threadIdx.x;
    if (e >= EE) return;
    int s = __ldg(&src[e]);
    int d = __ldg(&dst[e]);
    float w = __ldg(&ew[e]) * __ldg(&g_dinv[s]);
    g_we[e] = w;
    float4 x = g_Xp[s];
    float4* p = &g_aggX[d];
    asm volatile("red.global.add.v4.f32 [%0], {%1, %2, %3, %4};" ::
                 "l"(p), "f"(x.x * w), "f"(x.y * w), "f"(x.z * w), "f"(0.0f)
                 : "memory");
}

// K4: A = dinv*aggX + dinv^2*Xp ; out1 = leaky(A @ W1 + b1) -> g_h ; g_agg = 0
__global__ void k_mid(const float* __restrict__ W1, const float* __restrict__ b1) {
    __shared__ float sW[48];
    __shared__ float sb[16];
    if (threadIdx.x < 48) sW[threadIdx.x] = W1[threadIdx.x];
    if (threadIdx.x < 16) sb[threadIdx.x] = b1[threadIdx.x];
    __syncthreads();
    int i = blockIdx.x * blockDim.x + threadIdx.x;
    if (i >= NN) return;
    float di = g_dinv[i];
    float di2 = di * di;
    float4 ax = g_aggX[i];
    float4 xp = g_Xp[i];
    float a0 = di * ax.x + di2 * xp.x;
    float a1 = di * ax.y + di2 * xp.y;
    float a2 = di * ax.z + di2 * xp.z;
#pragma unroll
    for (int c = 0; c < 4; c++) {
        float4 h;
        h.x = lrelu(a0 * sW[4 * c + 0] + a1 * sW[16 + 4 * c + 0] + a2 * sW[32 + 4 * c + 0] + sb[4 * c + 0]);
        h.y = lrelu(a0 * sW[4 * c + 1] + a1 * sW[16 + 4 * c + 1] + a2 * sW[32 + 4 * c + 1] + sb[4 * c + 1]);
        h.z = lrelu(a0 * sW[4 * c + 2] + a1 * sW[16 + 4 * c + 2] + a2 * sW[32 + 4 * c + 2] + sb[4 * c + 2]);
        h.w = lrelu(a0 * sW[4 * c + 3] + a1 * sW[16 + 4 * c + 3] + a2 * sW[32 + 4 * c + 3] + sb[4 * c + 3]);
        g_h[i * 4 + c] = h;
        g_agg[i * 4 + c] = make_float4(0.f, 0.f, 0.f, 0.f);
    }
}

// K5: layer-2 edge scatter on 16-dim v. 4 threads per edge, one float4 chunk each.
// g_agg[dst] += g_we[e] * g_h[src]     (dinv[dst] and self-loop applied later)
__global__ void __launch_bounds__(256) k_edge2(const int* __restrict__ src,
                                               const int* __restrict__ dst) {
    unsigned int t = blockIdx.x * blockDim.x + threadIdx.x;
    if (t >= 4u * EE) return;
    int e = (int)(t >> 2);
    int c = (int)(t & 3u);
    int s = __ldg(&src[e]);
    int d = __ldg(&dst[e]);
    float w = __ldg(&g_we[e]);
    float4 h = g_h[s * 4 + c];
    float4* p = &g_agg[d * 4 + c];
    asm volatile("red.global.add.v4.f32 [%0], {%1, %2, %3, %4};" ::
                 "l"(p), "f"(h.x * w), "f"(h.y * w), "f"(h.z * w), "f"(h.w * w)
                 : "memory");
}

// K6: u = dinv*agg + dinv^2*v ; out2 = leaky(u @ W2 + b2) -> g_h
__global__ void k_post(const float* __restrict__ W2, const float* __restrict__ b2) {
    __shared__ float sW[256];
    __shared__ float sb[16];
    for (int t = threadIdx.x; t < 256; t += blockDim.x) sW[t] = W2[t];
    if (threadIdx.x < 16) sb[threadIdx.x] = b2[threadIdx.x];
    __syncthreads();
    int i = blockIdx.x * blockDim.x + threadIdx.x;
    if (i >= NN) return;
    float di = g_dinv[i];
    float di2 = di * di;
    float u[16];
#pragma unroll
    for (int c = 0; c < 4; c++) {
        float4 a = g_agg[i * 4 + c];
        float4 v = g_h[i * 4 + c];
        u[4 * c + 0] = di * a.x + di2 * v.x;
        u[4 * c + 1] = di * a.y + di2 * v.y;
        u[4 * c + 2] = di * a.z + di2 * v.z;
        u[4 * c + 3] = di * a.w + di2 * v.w;
    }
    float4 o[4];
#pragma unroll
    for (int c = 0; c < 4; c++) {
        float h0 = sb[4 * c + 0], h1 = sb[4 * c + 1], h2 = sb[4 * c + 2], h3 = sb[4 * c + 3];
#pragma unroll
        for (int k = 0; k < 16; k++) {
            float uk = u[k];
            h0 += uk * sW[k * 16 + 4 * c + 0];
            h1 += uk * sW[k * 16 + 4 * c + 1];
            h2 += uk * sW[k * 16 + 4 * c + 2];
            h3 += uk * sW[k * 16 + 4 * c + 3];
        }
        o[c] = make_float4(lrelu(h0), lrelu(h1), lrelu(h2), lrelu(h3));
    }
#pragma unroll
    for (int c = 0; c < 4; c++) g_h[i * 4 + c] = o[c];
}

// K7: mean pool per graph. One block (128 threads) per graph; binary search bounds.
__global__ void k_pool(const int* __restrict__ B) {
    int g = blockIdx.x;
    int lo = 0, hi = NN;
    while (lo < hi) { int m = (lo + hi) >> 1; if (__ldg(&B[m]) < g) lo = m + 1; else hi = m; }
    int start = lo;
    lo = start; hi = NN;
    while (lo < hi) { int m = (lo + hi) >> 1; if (__ldg(&B[m]) < g + 1) lo = m + 1; else hi = m; }
    int end = lo;
    int cnt = end - start;

    int c = threadIdx.x & 3;
    int k = threadIdx.x >> 2;  // 0..31
    float4 acc = make_float4(0.f, 0.f, 0.f, 0.f);
    for (int n = start + k; n < end; n += 32) {
        float4 v = g_h[n * 4 + c];
        acc.x += v.x; acc.y += v.y; acc.z += v.z; acc.w += v.w;
    }
    __shared__ float4 sm[128];
    sm[threadIdx.x] = acc;
    __syncthreads();
#pragma unroll
    for (int off = 64; off >= 4; off >>= 1) {
        if (threadIdx.x < off) {
            float4 o = sm[threadIdx.x + off];
            float4 m = sm[threadIdx.x];
            sm[threadIdx.x] = make_float4(m.x + o.x, m.y + o.y, m.z + o.z, m.w + o.w);
        }
        __syncthreads();
    }
    if (threadIdx.x < 4) {
        float inv = 1.0f / fmaxf((float)cnt, 1.0f);
        float4 s = sm[threadIdx.x];
        g_pooled[g * 4 + threadIdx.x] = make_float4(s.x * inv, s.y * inv, s.z * inv, s.w * inv);
    }
}

// K8: MLP heads. One thread per graph.
__global__ void k_mlp(const float* __restrict__ Wp1, const float* __restrict__ bp1,
                      const float* __restrict__ Wp2, const float* __restrict__ bp2,
                      const float* __restrict__ Wp3, const float* __restrict__ bp3,
                      const float* __restrict__ Wt1, const float* __restrict__ bt1,
                      const float* __restrict__ Wt2, const float* __restrict__ bt2,
                      const float* __restrict__ Wt3, const float* __restrict__ bt3,
                      float* __restrict__ out) {
    __shared__ float sWp1[256], sWp2[256], sWp3[32], sWt1[256], sWt2[256], sWt3[32];
    __shared__ float sbp1[16], sbp2[16], sbp3[2], sbt1[16], sbt2[16], sbt3[2];
    for (int t = threadIdx.x; t < 256; t += blockDim.x) {
        sWp1[t] = Wp1[t]; sWp2[t] = Wp2[t]; sWt1[t] = Wt1[t]; sWt2[t] = Wt2[t];
    }
    if (threadIdx.x < 32) { sWp3[threadIdx.x] = Wp3[threadIdx.x]; sWt3[threadIdx.x] = Wt3[threadIdx.x]; }
    if (threadIdx.x < 16) {
        sbp1[threadIdx.x] = bp1[threadIdx.x]; sbp2[threadIdx.x] = bp2[threadIdx.x];
        sbt1[threadIdx.x] = bt1[threadIdx.x]; sbt2[threadIdx.x] = bt2[threadIdx.x];
    }
    if (threadIdx.x < 2) { sbp3[threadIdx.x] = bp3[threadIdx.x]; sbt3[threadIdx.x] = bt3[threadIdx.x]; }
    __syncthreads();

    int g = blockIdx.x * blockDim.x + threadIdx.x;
    if (g >= GG) return;
    float p[16];
#pragma unroll
    for (int c = 0; c < 4; c++) {
        float4 v = g_pooled[g * 4 + c];
        p[4 * c + 0] = v.x; p[4 * c + 1] = v.y; p[4 * c + 2] = v.z; p[4 * c + 3] = v.w;
    }
    float a[16], b[16];
#pragma unroll
    for (int j = 0; j < 16; j++) {
        float s = sbp1[j];
#pragma unroll
        for (int k = 0; k < 16; k++) s += p[k] * sWp1[k * 16 + j];
        a[j] = lrelu(s);
    }
#pragma unroll
    for (int j = 0; j < 16; j++) {
        float s = sbp2[j];
#pragma unroll
        for (int k = 0; k < 16; k++) s += a[k] * sWp2[k * 16 + j];
        b[j] = lrelu(s);
    }
    float phi0 = sbp3[0], phi1 = sbp3[1];
#pragma unroll
    for (int k = 0; k < 16; k++) { phi0 += b[k] * sWp3[k * 2 + 0]; phi1 += b[k] * sWp3[k * 2 + 1]; }
#pragma unroll
    for (int j = 0; j < 16; j++) {
        float s = sbt1[j];
#pragma unroll
        for (int k = 0; k < 16; k++) s += p[k] * sWt1[k * 16 + j];
        a[j] = lrelu(s);
    }
#pragma unroll
    for (int j = 0; j < 16; j++) {
        float s = sbt2[j];
#pragma unroll
        for (int k = 0; k < 16; k++) s += a[k] * sWt2[k * 16 + j];
        b[j] = lrelu(s);
    }
    float th0 = sbt3[0], th1 = sbt3[1];
#pragma unroll
    for (int k = 0; k < 16; k++) { th0 += b[k] * sWt3[k * 2 + 0]; th1 += b[k] * sWt3[k * 2 + 1]; }

    out[g * 4 + 0] = phi0;
    out[g * 4 + 1] = phi1;
    out[g * 4 + 2] = th0;
    out[g * 4 + 3] = th1;
}

// ---------------------------------------------------------------------------
extern "C" void kernel_launch(void* const* d_in, const int* in_sizes, int n_in,
                              void* d_out, int out_size) {
    const float* X   = (const float*)d_in[0];
    const int*   ei  = (const int*)d_in[1];
    const float* ew  = (const float*)d_in[2];
    const int*   Bt  = (const int*)d_in[3];
    int base = 4;
    if (base < n_in && in_sizes[base] == 1) base++;  // skip scalar num_graphs
    const float* W1  = (const float*)d_in[base + 0];
    const float* b1  = (const float*)d_in[base + 1];
    const float* W2  = (const float*)d_in[base + 2];
    const float* b2  = (const float*)d_in[base + 3];
    const float* Wp1 = (const float*)d_in[base + 4];
    const float* bp1 = (const float*)d_in[base + 5];
    const float* Wp2 = (const float*)d_in[base + 6];
    const float* bp2 = (const float*)d_in[base + 7];
    const float* Wp3 = (const float*)d_in[base + 8];
    const float* bp3 = (const float*)d_in[base + 9];
    const float* Wt1 = (const float*)d_in[base + 10];
    const float* bt1 = (const float*)d_in[base + 11];
    const float* Wt2 = (const float*)d_in[base + 12];
    const float* bt2 = (const float*)d_in[base + 13];
    const float* Wt3 = (const float*)d_in[base + 14];
    const float* bt3 = (const float*)d_in[base + 15];

    const int* src = ei;
    const int* dst = ei + EE;
    float* out = (float*)d_out;

    k_init<<<NN / 256, 256>>>();
    k_deg<<<EE / 4 / 256, 256>>>(dst, ew);
    k_prep<<<NN / 256, 256>>>(X);
    k_edge1<<<EE / 256, 256>>>(src, dst, ew);
    k_mid<<<NN / 256, 256>>>(W1, b1);
    k_edge2<<<(4u * EE) / 256, 256>>>(src, dst);
    k_post<<<NN / 256, 256>>>(W2, b2);
    k_pool<<<GG, 128>>>(Bt);
    k_mlp<<<(GG + 255) / 256, 256>>>(Wp1, bp1, Wp2, bp2, Wp3, bp3,
                                     Wt1, bt1, Wt2, bt2, Wt3, bt3, out);
}